// round 9
// baseline (speedup 1.0000x reference)
#include <cuda_runtime.h>
#include <math.h>
#include <limits.h>

// CRF loss: out[b] = logZ(b) - label_score(b).  B=512, S=512, L=128.
//
// Scaled linear-space forward recursion, ONE batch per 256-thread block,
// targeted at 3 CTAs/SM (24 warps/SM) via <=85 registers.
// Thread layout: warp w lane l -> column j = 16w + (l&15), half h = l>>4.
// Thread (j,h) holds E rows [64h,64h+64) of column j as 32 f32x2 regs.
// Per step: partial GEMV (16 LDS.128 broadcast + 32 FFMA2, 2 acc chains),
// halves combined with one shfl_xor(16); h==0 lanes own ALL scalar work
// (exp, rcp, U store, x prefetch) -> zero redundancy.
// U double-buffered in bank-skewed shared, ONE __syncthreads per step.
// Grid = B blocks, longest-first (LPT) via bitonic-sorted permutation.

#define LDIM 128

__device__ int d_perm[1024];

__device__ __forceinline__ unsigned long long pack_f32x2(float lo, float hi) {
    unsigned long long r;
    asm("mov.b64 %0, {%1, %2};" : "=l"(r) : "f"(lo), "f"(hi));
    return r;
}
__device__ __forceinline__ void unpack_f32x2(unsigned long long v, float& lo, float& hi) {
    asm("mov.b64 {%0, %1}, %2;" : "=f"(lo), "=f"(hi) : "l"(v));
}
__device__ __forceinline__ unsigned long long fma_f32x2(unsigned long long a,
                                                        unsigned long long b,
                                                        unsigned long long c) {
    unsigned long long d;
    asm("fma.rn.f32x2 %0, %1, %2, %3;" : "=l"(d) : "l"(a), "l"(b), "l"(c));
    return d;
}
__device__ __forceinline__ unsigned long long add_f32x2(unsigned long long a,
                                                        unsigned long long b) {
    unsigned long long d;
    asm("add.rn.f32x2 %0, %1, %2;" : "=l"(d) : "l"(a), "l"(b));
    return d;
}
__device__ __forceinline__ float rcp_approx(float x) {
    float r;
    asm("rcp.approx.ftz.f32 %0, %1;" : "=f"(r) : "f"(x));
    return r;
}

// ------------- longest-first permutation (bitonic, 1 block) ---------------
__global__ void sort_len_kernel(const int* __restrict__ length, int B, int S)
{
    __shared__ int key[1024];
    __shared__ int val[1024];
    const int t = threadIdx.x;

    int k = INT_MAX;
    if (t < B) {
        int L = length[t];
        L = L < 1 ? 1 : (L > S ? S : L);
        k = -L;               // ascending on -len => longest first
    }
    key[t] = k;
    val[t] = t;
    __syncthreads();

    for (int kk = 2; kk <= 1024; kk <<= 1) {
        for (int s = kk >> 1; s > 0; s >>= 1) {
            int p = t ^ s;
            if (p > t) {
                bool up = ((t & kk) == 0);
                int kt = key[t], kp = key[p];
                if ((kt > kp) == up) {
                    key[t] = kp; key[p] = kt;
                    int vt = val[t]; val[t] = val[p]; val[p] = vt;
                }
            }
            __syncthreads();
        }
    }
    if (t < B) d_perm[t] = val[t];
}

// ------------------------------ main kernel --------------------------------
// skew(i) = i + 4*(i>>5): reads (2 bcast addrs/instr) and writes (16 lanes,
// consecutive banks) are all single-wavefront. Max index 139 < 144.
__global__ __launch_bounds__(256, 3)
void crf_forward_kernel(const float* __restrict__ input,
                        const int*   __restrict__ label,
                        const int*   __restrict__ length,
                        const float* __restrict__ trans,
                        float* __restrict__ out,
                        int S)
{
    __shared__ __align__(16) float u_sh[2][144];
    __shared__ float wred[8];
    __shared__ float s_x00;
    __shared__ float s_ls;

    const int tid = threadIdx.x;
    const int w   = tid >> 5;
    const int l   = tid & 31;
    const int h   = l >> 4;              // half of the i-range
    const int j   = w * 16 + (l & 15);   // state column 0..127

    const int b = d_perm[blockIdx.x];

    int len = length[b];
    len = len < 1 ? 1 : (len > S ? S : len);

    const float* xb   = input + (size_t)b * S * LDIM;
    const int*   labb = label + (size_t)b * S;

    // ---------------- label score (point + transition) ----------------
    {
        float ls = 0.f;
        for (int t = tid; t < len; t += 256) {
            int lab = labb[t];
            ls += xb[(size_t)t * LDIM + lab];
            if (t + 1 < len) ls += trans[lab * LDIM + labb[t + 1]];
        }
        #pragma unroll
        for (int o = 16; o > 0; o >>= 1)
            ls += __shfl_xor_sync(0xffffffffu, ls, o);
        if (l == 0) wred[w] = ls;
        __syncthreads();
        if (tid == 0) {
            float acc = 0.f;
            #pragma unroll
            for (int i = 0; i < 8; i++) acc += wred[i];
            s_ls = acc;
        }
    }

    // ------ E rows [64h, 64h+64) of column j: 32 f32x2 registers -------
    unsigned long long E2[32];
    #pragma unroll
    for (int k = 0; k < 32; k++) {
        int i0 = 64 * h + 2 * k;
        float lo = __expf(trans[(i0)     * LDIM + j]);
        float hi = __expf(trans[(i0 + 1) * LDIM + j]);
        E2[k] = pack_f32x2(lo, hi);
    }

    // ---------------- init U (h==0 lanes own the state) -----------------
    const int widx = j + ((j >> 5) << 2);       // skewed store index
    float x0 = xb[j];
    if (tid == 0) s_x00 = x0;
    __syncthreads();
    const float X00 = s_x00;
    float U = __expf(x0 - X00);
    if (h == 0) u_sh[0][widx] = U;

    // x prefetch, 2 steps deep; uniform clamped offset, per-thread base
    const float* pj = xb + j;
    const int omax = (len - 1) * LDIM;           // uniform
    int o1 = LDIM     < omax ? LDIM     : omax;
    int o2 = 2 * LDIM < omax ? 2 * LDIM : omax;
    float xA = pj[o1];                           // x for t=1
    float xB = pj[o2];                           // x for t=2

    float alog = 0.f;                            // tid 0 only
    __syncthreads();

    // ulonglong2 read bases: h=0 -> chunk 0, h=1 -> chunk 18 (float 72)
    const int rbase = 18 * h;

    int cur = 0;

    // ---------------- forward recursion: t = 1 .. len-1 -----------------
    for (int t = 1; t < len; t++) {
        const int nxt = cur ^ 1;
        const float r  = rcp_approx(u_sh[cur][0]);
        const float ex = __expf(xA);

        // rotate prefetch (x for t+2), uniform offset
        xA = xB;
        int on = (t + 2) * LDIM;
        if (on > omax) on = omax;
        xB = pj[on];

        // partial GEMV over this thread's 64 rows:
        // chunks c=0..15 at ulonglong2 index rbase + c + (c>>3)
        const ulonglong2* q = (const ulonglong2*)u_sh[cur] + rbase;
        unsigned long long acc0 = 0ull, acc1 = 0ull;
        #pragma unroll
        for (int c = 0; c < 16; c++) {
            ulonglong2 ua = q[c + (c >> 3)];
            acc0 = fma_f32x2(ua.x, E2[2 * c + 0], acc0);
            acc1 = fma_f32x2(ua.y, E2[2 * c + 1], acc1);
        }
        unsigned long long sacc = add_f32x2(acc0, acc1);
        float s_lo, s_hi;
        unpack_f32x2(sacc, s_lo, s_hi);
        float s = s_lo + s_hi;

        // combine halves (lane bit 4)
        s += __shfl_xor_sync(0xffffffffu, s, 16);

        if (h == 0) {
            U = s * (r * ex);
            u_sh[nxt][widx] = U;
        }
        if (tid == 0)
            alog += __logf(r);
        cur = nxt;
        __syncthreads();
    }

    // ------- z = x00 - alog + log(sum_j U);  out = z - label_score ------
    float es = (h == 0) ? U : 0.f;
    #pragma unroll
    for (int o = 8; o > 0; o >>= 1)              // sum over lower 16 lanes
        es += __shfl_xor_sync(0xffffffffu, es, o);
    es += __shfl_xor_sync(0xffffffffu, es, 16);  // fold (h1 zeros anyway)
    if (l == 0) wred[w] = es;
    __syncthreads();
    if (tid == 0) {
        float ssum = 0.f;
        #pragma unroll
        for (int i = 0; i < 8; i++) ssum += wred[i];
        out[b] = X00 - alog + logf(ssum) - s_ls;
    }
}

extern "C" void kernel_launch(void* const* d_in, const int* in_sizes, int n_in,
                              void* d_out, int out_size)
{
    const float* input  = (const float*)d_in[0];   // (B, S, L) f32
    const int*   label  = (const int*)  d_in[1];   // (B, S) i32
    const int*   length = (const int*)  d_in[2];   // (B,) i32
    const float* trans  = (const float*)d_in[3];   // (L, L) f32
    float* out = (float*)d_out;                    // (B, 1) f32

    const int B = in_sizes[2];
    const int S = in_sizes[1] / B;

    sort_len_kernel<<<1, 1024>>>(length, B, S);
    crf_forward_kernel<<<B, 256>>>(input, label, length, trans, out, S);
}

// round 10
// speedup vs baseline: 1.9617x; 1.9617x over previous
#include <cuda_runtime.h>
#include <math.h>
#include <limits.h>

// CRF loss: out[b] = logZ(b) - label_score(b).  B=512, S=512, L=128.
//
// Scaled linear-space forward recursion, TWO adjacent-length batches per
// 256-thread block. Lane layout: warp w, lane l -> jp = 8w + (l&7),
// quarter q = l>>3. Thread holds E rows [32q,32q+32) of TWO columns
// {jp, jp+64} (32 f32x2 regs) -> each LDS.128 of U feeds 4 FFMA2
// (halves shared-memory crossbar traffic vs 1-column layout).
// Quarter partials combine via shfl_xor(8,16). Every lane then owns one
// (batch=q>>1, column=jp+64*(q&1)) scalar stream: x prefetch, exp, rcp
// scale, U store -- fully uniform, zero redundancy. U double-buffered in
// bank-skewed shared (skew i+4*(i>>5)); ONE __syncthreads per step.
// Pairs sorted longest-first with co-residency remap.

#define LDIM 128

__device__ int d_perm[1024];

__device__ __forceinline__ unsigned long long pack_f32x2(float lo, float hi) {
    unsigned long long r;
    asm("mov.b64 %0, {%1, %2};" : "=l"(r) : "f"(lo), "f"(hi));
    return r;
}
__device__ __forceinline__ void unpack_f32x2(unsigned long long v, float& lo, float& hi) {
    asm("mov.b64 {%0, %1}, %2;" : "=f"(lo), "=f"(hi) : "l"(v));
}
__device__ __forceinline__ unsigned long long fma_f32x2(unsigned long long a,
                                                        unsigned long long b,
                                                        unsigned long long c) {
    unsigned long long d;
    asm("fma.rn.f32x2 %0, %1, %2, %3;" : "=l"(d) : "l"(a), "l"(b), "l"(c));
    return d;
}
__device__ __forceinline__ unsigned long long add_f32x2(unsigned long long a,
                                                        unsigned long long b) {
    unsigned long long d;
    asm("add.rn.f32x2 %0, %1, %2;" : "=l"(d) : "l"(a), "l"(b));
    return d;
}
__device__ __forceinline__ float rcp_approx(float x) {
    float r;
    asm("rcp.approx.ftz.f32 %0, %1;" : "=f"(r) : "f"(x));
    return r;
}
__device__ __forceinline__ float hsum2(unsigned long long a, unsigned long long b) {
    unsigned long long s = add_f32x2(a, b);
    float lo, hi;
    unpack_f32x2(s, lo, hi);
    return lo + hi;
}

// ------------- longest-first permutation (bitonic, 1 block) ---------------
__global__ void sort_len_kernel(const int* __restrict__ length, int B, int S)
{
    __shared__ int key[1024];
    __shared__ int val[1024];
    const int t = threadIdx.x;

    int k = INT_MAX;
    if (t < B) {
        int L = length[t];
        L = L < 1 ? 1 : (L > S ? S : L);
        k = -L;               // ascending on -len => longest first
    }
    key[t] = k;
    val[t] = t;
    __syncthreads();

    for (int kk = 2; kk <= 1024; kk <<= 1) {
        for (int s = kk >> 1; s > 0; s >>= 1) {
            int p = t ^ s;
            if (p > t) {
                bool up = ((t & kk) == 0);
                int kt = key[t], kp = key[p];
                if ((kt > kp) == up) {
                    key[t] = kp; key[p] = kt;
                    int vt = val[t]; val[t] = val[p]; val[p] = vt;
                }
            }
            __syncthreads();
        }
    }
    if (t < B) d_perm[t] = val[t];
}

// ------------------------------ main kernel --------------------------------
__global__ __launch_bounds__(256, 2)
void crf_forward_kernel(const float* __restrict__ input,
                        const int*   __restrict__ label,
                        const int*   __restrict__ length,
                        const float* __restrict__ trans,
                        float* __restrict__ out,
                        int S, int B, int npairs, int nfirst)
{
    // skew(i) = i + 4*(i>>5); max index 139 < 144. Reads: quarter q starts
    // at float 36q (distinct banks), 8 contiguous 16B chunks. Writes: q
    // groups land on disjoint bank ranges. All single-wavefront.
    __shared__ __align__(16) float u_sh[2][2][144];   // [buf][g][state]
    __shared__ float wred[2][8];
    __shared__ float wlog[2][8];
    __shared__ float s_x00[2];
    __shared__ float s_ls[2];

    const int tid = threadIdx.x;
    const int w   = tid >> 5;
    const int l   = tid & 31;
    const int q   = l >> 3;              // row quarter / ownership code
    const int jp  = w * 8 + (l & 7);     // column pair base 0..63
    const int g   = q >> 1;              // owned batch
    const int jo  = jp + ((q & 1) << 6); // owned column

    // co-residency remap: blocks sharing an SM get complementary pairs
    const int bid = blockIdx.x;
    const int pid = (bid < nfirst) ? bid : (npairs - 1 - (bid - nfirst));

    const int  b0   = d_perm[2 * pid];
    const bool has1 = (2 * pid + 1 < B);
    const int  b1   = has1 ? d_perm[2 * pid + 1] : b0;

    int len0 = length[b0]; len0 = len0 < 1 ? 1 : (len0 > S ? S : len0);
    int len1 = len0;
    if (has1) { len1 = length[b1]; len1 = len1 < 1 ? 1 : (len1 > S ? S : len1); }
    // sorted order: len0 >= len1.

    const float* xb0 = input + (size_t)b0 * S * LDIM;
    const float* xb1 = input + (size_t)b1 * S * LDIM;
    const float* xbg = g ? xb1 : xb0;
    const int    lenown = g ? len1 : len0;

    // ---------------- label scores (both batches) ----------------------
    #pragma unroll
    for (int gg = 0; gg < 2; gg++) {
        const float* xb = gg ? xb1 : xb0;
        const int* labb = label + (size_t)(gg ? b1 : b0) * S;
        const int  len  = gg ? (has1 ? len1 : 0) : len0;
        float ls = 0.f;
        for (int t = tid; t < len; t += 256) {
            int lab = labb[t];
            ls += xb[(size_t)t * LDIM + lab];
            if (t + 1 < len) ls += trans[lab * LDIM + labb[t + 1]];
        }
        #pragma unroll
        for (int o = 16; o > 0; o >>= 1)
            ls += __shfl_xor_sync(0xffffffffu, ls, o);
        if (l == 0) wred[gg][w] = ls;
    }
    __syncthreads();
    if (tid < 2) {
        float acc = 0.f;
        #pragma unroll
        for (int i = 0; i < 8; i++) acc += wred[tid][i];
        s_ls[tid] = acc;
    }

    // --- E rows [32q,32q+32) of columns jp and jp+64: 32 f32x2 regs ----
    unsigned long long E2A[16], E2B[16];
    #pragma unroll
    for (int k = 0; k < 16; k++) {
        int i0 = 32 * q + 2 * k;
        E2A[k] = pack_f32x2(__expf(trans[(i0)     * LDIM + jp]),
                            __expf(trans[(i0 + 1) * LDIM + jp]));
        E2B[k] = pack_f32x2(__expf(trans[(i0)     * LDIM + jp + 64]),
                            __expf(trans[(i0 + 1) * LDIM + jp + 64]));
    }

    // ---------------- init U (every lane owns one (g, jo) stream) -------
    const int wido = jo + ((jo >> 5) << 2);   // skewed store index
    const float* pj = xbg + jo;
    float x0 = pj[0];
    if (tid == 0)  s_x00[0] = x0;             // g=0, jo=0
    if (tid == 16) s_x00[1] = x0;             // g=1, jo=0
    __syncthreads();
    float U = __expf(x0 - s_x00[g]);
    u_sh[0][g][wido] = U;

    const int omax = (lenown - 1) * LDIM;
    int o1 = LDIM     < omax ? LDIM     : omax;
    int o2 = 2 * LDIM < omax ? 2 * LDIM : omax;
    float xA = pj[o1];                         // x for t=1
    float xB = pj[o2];                         // x for t=2

    float alog = 0.f;                          // rotating owner lanes only
    __syncthreads();

    int cur = 0;

    // ---------------- forward recursion: t = 1 .. len0-1 ----------------
    for (int t = 1; t < len0; t++) {
        const int nxt = cur ^ 1;
        const float r  = rcp_approx(u_sh[cur][g][0]);   // own batch's U[0]
        const float ex = __expf(xA);

        // rotate prefetch (x for t+2)
        xA = xB;
        int on = (t + 2) * LDIM;
        if (on > omax) on = omax;
        xB = pj[on];

        // partial GEMVs: 8 LDS.128 per batch, each feeding 4 FFMA2
        const ulonglong2* p0 = (const ulonglong2*)(u_sh[cur][0] + 36 * q);
        const ulonglong2* p1 = (const ulonglong2*)(u_sh[cur][1] + 36 * q);
        unsigned long long aA0 = 0ull, aA1 = 0ull, aB0 = 0ull, aB1 = 0ull;
        unsigned long long cA0 = 0ull, cA1 = 0ull, cB0 = 0ull, cB1 = 0ull;
        #pragma unroll
        for (int c = 0; c < 8; c++) {
            ulonglong2 ua = p0[c];
            ulonglong2 va = p1[c];
            aA0 = fma_f32x2(ua.x, E2A[2 * c + 0], aA0);
            aA1 = fma_f32x2(ua.y, E2A[2 * c + 1], aA1);
            aB0 = fma_f32x2(ua.x, E2B[2 * c + 0], aB0);
            aB1 = fma_f32x2(ua.y, E2B[2 * c + 1], aB1);
            cA0 = fma_f32x2(va.x, E2A[2 * c + 0], cA0);
            cA1 = fma_f32x2(va.y, E2A[2 * c + 1], cA1);
            cB0 = fma_f32x2(va.x, E2B[2 * c + 0], cB0);
            cB1 = fma_f32x2(va.y, E2B[2 * c + 1], cB1);
        }
        float s0A = hsum2(aA0, aA1);   // batch0, col jp   (quarter partial)
        float s0B = hsum2(aB0, aB1);   // batch0, col jp+64
        float s1A = hsum2(cA0, cA1);   // batch1, col jp
        float s1B = hsum2(cB0, cB1);   // batch1, col jp+64

        // reduce over quarters (lane bits 3,4)
        #pragma unroll
        for (int oo = 8; oo <= 16; oo <<= 1) {
            s0A += __shfl_xor_sync(0xffffffffu, s0A, oo);
            s0B += __shfl_xor_sync(0xffffffffu, s0B, oo);
            s1A += __shfl_xor_sync(0xffffffffu, s1A, oo);
            s1B += __shfl_xor_sync(0xffffffffu, s1B, oo);
        }

        // each lane picks its owned (batch, column) sum
        float sb0 = (q & 1) ? s0B : s0A;
        float sb1 = (q & 1) ? s1B : s1A;
        float sown = g ? sb1 : sb0;

        float Un = sown * (r * ex);
        bool  act = (t < lenown);            // batch-1 freezes at len1
        U = act ? Un : U;
        u_sh[nxt][g][wido] = U;
        if ((l & 15) == 0 && w == (t & 7) && act)   // lanes 0,16 of warp t&7
            alog += __logf(r);
        cur = nxt;
        __syncthreads();
    }

    // ---------------- outputs ------------------------------------------
    float es0 = (g == 0) ? U : 0.f;
    float es1 = (g == 1) ? U : 0.f;
    #pragma unroll
    for (int oo = 16; oo > 0; oo >>= 1) {
        es0 += __shfl_xor_sync(0xffffffffu, es0, oo);
        es1 += __shfl_xor_sync(0xffffffffu, es1, oo);
    }
    if (l == 0)  { wred[0][w] = es0; wred[1][w] = es1; wlog[0][w] = alog; }
    if (l == 16) { wlog[1][w] = alog; }
    __syncthreads();
    if (tid == 0) {
        float ss0 = 0.f, al0 = 0.f;
        #pragma unroll
        for (int i = 0; i < 8; i++) { ss0 += wred[0][i]; al0 += wlog[0][i]; }
        out[b0] = s_x00[0] - al0 + logf(ss0) - s_ls[0];
        if (has1) {
            float ss1 = 0.f, al1 = 0.f;
            #pragma unroll
            for (int i = 0; i < 8; i++) { ss1 += wred[1][i]; al1 += wlog[1][i]; }
            out[b1] = s_x00[1] - al1 + logf(ss1) - s_ls[1];
        }
    }
}

extern "C" void kernel_launch(void* const* d_in, const int* in_sizes, int n_in,
                              void* d_out, int out_size)
{
    const float* input  = (const float*)d_in[0];   // (B, S, L) f32
    const int*   label  = (const int*)  d_in[1];   // (B, S) i32
    const int*   length = (const int*)  d_in[2];   // (B,) i32
    const float* trans  = (const float*)d_in[3];   // (L, L) f32
    float* out = (float*)d_out;                    // (B, 1) f32

    const int B = in_sizes[2];
    const int S = in_sizes[1] / B;

    const int npairs = (B + 1) / 2;
    const int nfirst = npairs > 148 ? 148 : npairs;

    sort_len_kernel<<<1, 1024>>>(length, B, S);
    crf_forward_kernel<<<npairs, 256>>>(input, label, length, trans, out,
                                        S, B, npairs, nfirst);
}